// round 16
// baseline (speedup 1.0000x reference)
#include <cuda_runtime.h>
#include <cuda_fp16.h>
#include <cstdint>

#define TOKENS 8192
#define DM 1024
#define DH 4096
#define NE 8
#define NSLOTS (TOKENS * 2)

// GEMM tiling: CTA 128x128x64, 8 warps (2m x 4n), warp tile 64x32, plain fp16 1-pass.
// SMEM: XOR-swizzled 128B rows (key = r&7). Stage = A(16KB)+B(16KB) = 32KB; 3 stages; 2 CTA/SM.
#define BM 128
#define BN 128
#define BK 64
#define NSTG 3
#define O_B 16384
#define STB 32768
#define SMEM_TOTAL (NSTG * STB)   // 98304

// ---------------- scratch globals (fp16) ----------------
__device__ __half g_xl[(size_t)TOKENS * DM];
__device__ __half g_w1t[(size_t)NE * DH * DM];   // [E][N=DH][K=DM]
__device__ __half g_w2t[(size_t)NE * DM * DH];   // [E][N=DM][K=DH]
__device__ __half g_h[(size_t)NSLOTS * DH];
__device__ float g_o[(size_t)NSLOTS * DM];
__device__ int g_top2[TOKENS];
__device__ int2 g_slots[TOKENS];
__device__ int g_counts[NE];
__device__ int g_offsets[NE];
__device__ int g_cursor[NE];
__device__ int g_tokens[NSLOTS];

// ---------------- PTX helpers ----------------
__device__ __forceinline__ uint32_t smem_u32(const void* p) {
    uint32_t a;
    asm("{ .reg .u64 t; cvta.to.shared.u64 t, %1; cvt.u32.u64 %0, t; }" : "=r"(a) : "l"(p));
    return a;
}
__device__ __forceinline__ void cp_async16(uint32_t dst, const void* src) {
    asm volatile("cp.async.cg.shared.global [%0], [%1], 16;" :: "r"(dst), "l"(src));
}
__device__ __forceinline__ void cp_commit() { asm volatile("cp.async.commit_group;" ::: "memory"); }
template <int N>
__device__ __forceinline__ void cp_wait() { asm volatile("cp.async.wait_group %0;" :: "n"(N) : "memory"); }

__device__ __forceinline__ void ldsm4(uint32_t* r, uint32_t addr) {
    asm volatile("ldmatrix.sync.aligned.m8n8.x4.shared.b16 {%0,%1,%2,%3}, [%4];"
                 : "=r"(r[0]), "=r"(r[1]), "=r"(r[2]), "=r"(r[3]) : "r"(addr));
}
__device__ __forceinline__ void mma_fp16(float* c, const uint32_t* a, const uint32_t* b) {
    asm volatile(
        "mma.sync.aligned.m16n8k16.row.col.f32.f16.f16.f32 "
        "{%0,%1,%2,%3}, {%4,%5,%6,%7}, {%8,%9}, {%0,%1,%2,%3};"
        : "+f"(c[0]), "+f"(c[1]), "+f"(c[2]), "+f"(c[3])
        : "r"(a[0]), "r"(a[1]), "r"(a[2]), "r"(a[3]), "r"(b[0]), "r"(b[1]));
}

// swizzled offset within a 128x128B tile: row r (0..127), 16B chunk c (0..7), key = r&7
__device__ __forceinline__ uint32_t swz(int r, int c) {
    return (uint32_t)r * 128u + (uint32_t)((c ^ (r & 7)) << 4);
}

// compensated accumulate: (s,c) += x*w with product error captured via FMA
__device__ __forceinline__ void comp_fma(float& s, float& c, float x, float w) {
    float p = x * w;
    float perr = fmaf(x, w, -p);
    float t = s + p;
    float z = t - s;
    float serr = (s - (t - z)) + (p - z);
    s = t;
    c += perr + serr;
}
__device__ __forceinline__ void comp_merge(float& s, float& c, float s2, float c2) {
    float t = s + s2;
    float z = t - s;
    float serr = (s - (t - z)) + (s2 - z);
    s = t;
    c += c2 + serr;
}

// ---------------- counter reset ----------------
__global__ void k_reset() { if (threadIdx.x < NE) g_counts[threadIdx.x] = 0; }

// ---------------- gating (top-2 per token, compensated fp32) ----------------
__global__ void k_gating(const float* __restrict__ x0, const float* __restrict__ Wg) {
    const int warp = threadIdx.x >> 5, lane = threadIdx.x & 31;
    const int t = blockIdx.x * (blockDim.x >> 5) + warp;
    float s[NE], c[NE];
#pragma unroll
    for (int e = 0; e < NE; e++) { s[e] = 0.f; c[e] = 0.f; }
    const float* x = x0 + (size_t)t * DM;
    for (int k = lane; k < DM; k += 32) {
        float xv = x[k];
        const float4 w0 = *reinterpret_cast<const float4*>(Wg + (size_t)k * NE);
        const float4 w1 = *reinterpret_cast<const float4*>(Wg + (size_t)k * NE + 4);
        comp_fma(s[0], c[0], xv, w0.x); comp_fma(s[1], c[1], xv, w0.y);
        comp_fma(s[2], c[2], xv, w0.z); comp_fma(s[3], c[3], xv, w0.w);
        comp_fma(s[4], c[4], xv, w1.x); comp_fma(s[5], c[5], xv, w1.y);
        comp_fma(s[6], c[6], xv, w1.z); comp_fma(s[7], c[7], xv, w1.w);
    }
#pragma unroll
    for (int off = 16; off > 0; off >>= 1)
#pragma unroll
        for (int e = 0; e < NE; e++) {
            float s2 = __shfl_xor_sync(0xffffffffu, s[e], off);
            float c2 = __shfl_xor_sync(0xffffffffu, c[e], off);
            comp_merge(s[e], c[e], s2, c2);
        }
    if (lane == 0) {
        double acc[NE];
#pragma unroll
        for (int e = 0; e < NE; e++) acc[e] = (double)s[e] + (double)c[e];
        int i1 = 0; double v1 = acc[0];
#pragma unroll
        for (int e = 1; e < NE; e++) if (acc[e] > v1) { v1 = acc[e]; i1 = e; }
        int i2 = -1; double v2 = -1.0e300;
#pragma unroll
        for (int e = 0; e < NE; e++) if (e != i1 && acc[e] > v2) { v2 = acc[e]; i2 = e; }
        g_top2[t] = i1 | (i2 << 8);
        atomicAdd(&g_counts[i1], 1);
        atomicAdd(&g_counts[i2], 1);
    }
}

// ---------------- cvt xl -> fp16 (vectorized) ----------------
__global__ void k_cvt_x(const float* __restrict__ x) {
    const size_t total4 = (size_t)TOKENS * DM / 4;
    const size_t stride = (size_t)gridDim.x * blockDim.x;
    for (size_t i = (size_t)blockIdx.x * blockDim.x + threadIdx.x; i < total4; i += stride) {
        float4 v = *reinterpret_cast<const float4*>(x + i * 4);
        __half2 h01 = __floats2half2_rn(v.x, v.y);
        __half2 h23 = __floats2half2_rn(v.z, v.w);
        *reinterpret_cast<uint2*>(g_xl + i * 4) =
            make_uint2(*(uint32_t*)&h01, *(uint32_t*)&h23);
    }
}

// ---------------- transpose-convert W[e][k][n] -> O[e][n][k] fp16 ----------
template <int K, int N, int MODE>
__global__ void k_wt(const float* __restrict__ W) {
    __shared__ float t[64][33];
    const int e = blockIdx.z;
    const int n0 = blockIdx.x * 32, k0 = blockIdx.y * 64;
    const float* Wp = W + (size_t)e * K * N;
    const int tx = threadIdx.x, ty = threadIdx.y;   // 32 x 8
#pragma unroll
    for (int j = 0; j < 8; j++)
        t[ty + j * 8][tx] = Wp[(size_t)(k0 + ty + j * 8) * N + n0 + tx];
    __syncthreads();
#pragma unroll
    for (int j = 0; j < 4; j++) {
        const int nl = ty + j * 8;
        __half2 h2 = __floats2half2_rn(t[tx * 2][nl], t[tx * 2 + 1][nl]);
        const size_t o = ((size_t)e * N + n0 + nl) * K + k0 + tx * 2;
        if (MODE == 0) *reinterpret_cast<uint32_t*>(g_w1t + o) = *(uint32_t*)&h2;
        else           *reinterpret_cast<uint32_t*>(g_w2t + o) = *(uint32_t*)&h2;
    }
}

// ---------------- scan (tiny) ----------------
__global__ void k_scan() {
    int s = 0;
    for (int e = 0; e < NE; e++) { g_offsets[e] = s; g_cursor[e] = s; s += g_counts[e]; }
}

// ---------------- parallel scatter ----------------
__global__ void k_scatter() {
    const int t = blockIdx.x * blockDim.x + threadIdx.x;
    const int p = g_top2[t];
    const int s1 = atomicAdd(&g_cursor[p & 0xff], 1);
    const int s2 = atomicAdd(&g_cursor[(p >> 8) & 0xff], 1);
    g_tokens[s1] = t;
    g_tokens[s2] = t;
    g_slots[t] = make_int2(s1, s2);
}

// ---------------- plain fp16 grouped GEMM (BK=64), fp32 accumulate ----------------
template <int KT, int NTOT, bool IS_G1>
__global__ __launch_bounds__(256, 2) void k_hmma(const float* __restrict__ bias) {
    const int e = blockIdx.z;
    const int cnt = g_counts[e];
    const int m0 = blockIdx.y * BM;
    if (m0 >= cnt) return;
    const int off = g_offsets[e];
    const int n0 = blockIdx.x * BN;
    const int tid = threadIdx.x;

    extern __shared__ char smem[];
    __shared__ int s_rows[BM];
    const uint32_t sb = smem_u32(smem);

    if (tid < BM) {
        int mm = m0 + tid;
        int mc = mm < cnt ? mm : cnt - 1;
        s_rows[tid] = IS_G1 ? g_tokens[off + mc] : (off + mc);
    }
    __syncthreads();

    const __half* A = IS_G1 ? g_xl : g_h;
    const __half* B = (IS_G1 ? g_w1t : g_w2t) + ((size_t)e * NTOT + n0) * KT;

    // fill plan: thread t -> row rF = t>>1, half hf = t&1 (chunks 4hf..4hf+3 of 8)
    const int rF = tid >> 1, hf = tid & 1;
    const int key = rF & 7;
    uint32_t dA[4];
#pragma unroll
    for (int i = 0; i < 4; i++)
        dA[i] = (uint32_t)rF * 128u + (uint32_t)(((hf * 4 + i) ^ key) << 4);
    const __half* a0 = A + (size_t)s_rows[rF] * KT + hf * 32;
    const __half* b0 = B + (size_t)rF * KT + hf * 32;

#define FILL(sidx, k0_) do {                                        \
        uint32_t _s = sb + (sidx) * STB;                            \
        _Pragma("unroll")                                           \
        for (int i = 0; i < 4; i++) {                               \
            cp_async16(_s + dA[i], a0 + (k0_) + i * 8);             \
            cp_async16(_s + O_B + dA[i], b0 + (k0_) + i * 8);       \
        }                                                           \
    } while (0)

    const int lane = tid & 31, wid = tid >> 5;
    const int warp_m = wid >> 2, warp_n = wid & 3;
    const int rowA = warp_m * 64 + (lane & 15);
    const int rowB = warp_n * 32 + ((lane >> 4) << 3) + (lane & 7);
    const uint32_t aoff = swz(rowA, lane >> 4);
    const uint32_t boff = swz(rowB, (lane >> 3) & 1);

    float acc[4][4][4];
#pragma unroll
    for (int i = 0; i < 4; i++)
#pragma unroll
        for (int j = 0; j < 4; j++)
#pragma unroll
            for (int q = 0; q < 4; q++) acc[i][j][q] = 0.f;

    constexpr int NKC = KT / BK;
    FILL(0, 0);  cp_commit();
    FILL(1, BK); cp_commit();

    for (int kc = 0; kc < NKC; kc++) {
        cp_wait<1>();
        __syncthreads();
        if (kc + 2 < NKC) { FILL((kc + 2) % NSTG, (kc + 2) * BK); }
        cp_commit();
        const uint32_t st = sb + (kc % NSTG) * STB;
#pragma unroll
        for (int k16 = 0; k16 < 4; k16++) {
            // chunk step of 2 per k16; disjoint bits -> pure XOR address update
            const uint32_t ab = st + (aoff ^ (k16 << 5));
            const uint32_t bb = st + O_B + (boff ^ (k16 << 5));
            uint32_t af[4][4], bf[2][4];
#pragma unroll
            for (int mt = 0; mt < 4; mt++) ldsm4(af[mt], ab + mt * 2048);
#pragma unroll
            for (int p = 0; p < 2; p++)   ldsm4(bf[p], bb + p * 2048);
#pragma unroll
            for (int mt = 0; mt < 4; mt++)
#pragma unroll
                for (int nt = 0; nt < 4; nt++)
                    mma_fp16(acc[mt][nt], af[mt], &bf[nt >> 1][(nt & 1) * 2]);
        }
    }
#undef FILL

    // ---- epilogue ----
    const int g = lane >> 2, c2 = (lane & 3) * 2;
    const float* bp = bias + (size_t)e * NTOT;
#pragma unroll
    for (int mt = 0; mt < 4; mt++) {
#pragma unroll
        for (int nt = 0; nt < 4; nt++) {
            const int n = n0 + warp_n * 32 + nt * 8 + c2;
            const float bv0 = __ldg(bp + n), bv1 = __ldg(bp + n + 1);
#pragma unroll
            for (int h = 0; h < 2; h++) {
                const int m = m0 + warp_m * 64 + mt * 16 + g + h * 8;
                if (m >= cnt) continue;
                float v0 = acc[mt][nt][h * 2 + 0] + bv0;
                float v1 = acc[mt][nt][h * 2 + 1] + bv1;
                if (IS_G1) {
                    __half2 h2 = __floats2half2_rn(fmaxf(v0, 0.f), fmaxf(v1, 0.f));
                    *reinterpret_cast<uint32_t*>(g_h + (size_t)(off + m) * DH + n) =
                        *(uint32_t*)&h2;
                } else {
                    float2 v = make_float2(v0, v1);
                    *reinterpret_cast<float2*>(g_o + (size_t)(off + m) * DM + n) = v;
                }
            }
        }
    }
}

// ---------------- combine out[t] = g_o[s1] + g_o[s2] ----------------
__global__ void k_combine(float* __restrict__ out) {
    const int i = blockIdx.x * blockDim.x + threadIdx.x;   // float4 index
    const int t = i >> 8, cc = i & 255;
    const int2 s = g_slots[t];
    const float4 a = *reinterpret_cast<const float4*>(g_o + (size_t)s.x * DM + cc * 4);
    const float4 b = *reinterpret_cast<const float4*>(g_o + (size_t)s.y * DM + cc * 4);
    float4 r = make_float4(a.x + b.x, a.y + b.y, a.z + b.z, a.w + b.w);
    *reinterpret_cast<float4*>(out + (size_t)t * DM + cc * 4) = r;
}

// ---------------- launch ----------------
extern "C" void kernel_launch(void* const* d_in, const int* in_sizes, int n_in,
                              void* d_out, int out_size) {
    const float* xl = (const float*)d_in[0];
    const float* x0 = (const float*)d_in[1];
    const float* Wg = (const float*)d_in[2];
    const float* W1 = (const float*)d_in[3];
    const float* b1 = (const float*)d_in[4];
    const float* W2 = (const float*)d_in[5];
    const float* b2 = (const float*)d_in[6];
    float* out = (float*)d_out;

    cudaFuncSetAttribute((const void*)k_hmma<DM, DH, true>,
                         cudaFuncAttributeMaxDynamicSharedMemorySize, SMEM_TOTAL);
    cudaFuncSetAttribute((const void*)k_hmma<DH, DM, false>,
                         cudaFuncAttributeMaxDynamicSharedMemorySize, SMEM_TOTAL);

    k_reset<<<1, 32>>>();
    k_gating<<<TOKENS / 8, 256>>>(x0, Wg);
    k_cvt_x<<<512, 256>>>(xl);
    k_wt<DM, DH, 0><<<dim3(DH / 32, DM / 64, NE), dim3(32, 8)>>>(W1);
    k_wt<DH, DM, 1><<<dim3(DM / 32, DH / 64, NE), dim3(32, 8)>>>(W2);
    k_scan<<<1, 1>>>();
    k_scatter<<<TOKENS / 256, 256>>>();
    // GEMM1: fp16 1-pass, relu -> h (fp16)
    k_hmma<DM, DH, true><<<dim3(DH / BN, TOKENS / BM, NE), 256, SMEM_TOTAL>>>(b1);
    // GEMM2: fp16 1-pass -> g_o
    k_hmma<DH, DM, false><<<dim3(DM / BN, TOKENS / BM, NE), 256, SMEM_TOTAL>>>(b2);
    k_combine<<<(TOKENS * DM / 4) / 256, 256>>>(out);
}

// round 17
// speedup vs baseline: 1.3473x; 1.3473x over previous
#include <cuda_runtime.h>
#include <cuda_fp16.h>
#include <cstdint>

#define TOKENS 8192
#define DM 1024
#define DH 4096
#define NE 8
#define NSLOTS (TOKENS * 2)

// GEMM tiling: CTA 128x128x32, 8 warps (2m x 4n), warp tile 64x32, plain fp16 1-pass.
// SMEM: XOR-swizzled 64B rows. Stage = A(8KB) + B(8KB) = 16KB; 4 stages; 2 CTA/SM.
// (R15 structure — measured 832.7us, tensor ~75%; BK=64 variants measured WORSE twice.)
#define BM 128
#define BN 128
#define BK 32
#define NSTG 4
#define O_B 8192
#define STB 16384
#define SMEM_TOTAL (NSTG * STB)   // 65536

// ---------------- scratch globals (fp16) ----------------
__device__ __half g_xl[(size_t)TOKENS * DM];
__device__ __half g_w1t[(size_t)NE * DH * DM];   // [E][N=DH][K=DM]
__device__ __half g_w2t[(size_t)NE * DM * DH];   // [E][N=DM][K=DH]
__device__ __half g_h[(size_t)NSLOTS * DH];
__device__ int g_top2[TOKENS];
__device__ int g_counts[NE];
__device__ int g_offsets[NE];
__device__ int g_cursor[NE];
__device__ int g_tokens[NSLOTS];

// ---------------- PTX helpers ----------------
__device__ __forceinline__ uint32_t smem_u32(const void* p) {
    uint32_t a;
    asm("{ .reg .u64 t; cvta.to.shared.u64 t, %1; cvt.u32.u64 %0, t; }" : "=r"(a) : "l"(p));
    return a;
}
__device__ __forceinline__ void cp_async16(uint32_t dst, const void* src) {
    asm volatile("cp.async.cg.shared.global [%0], [%1], 16;" :: "r"(dst), "l"(src));
}
__device__ __forceinline__ void cp_commit() { asm volatile("cp.async.commit_group;" ::: "memory"); }
template <int N>
__device__ __forceinline__ void cp_wait() { asm volatile("cp.async.wait_group %0;" :: "n"(N) : "memory"); }

__device__ __forceinline__ void ldsm4(uint32_t* r, uint32_t addr) {
    asm volatile("ldmatrix.sync.aligned.m8n8.x4.shared.b16 {%0,%1,%2,%3}, [%4];"
                 : "=r"(r[0]), "=r"(r[1]), "=r"(r[2]), "=r"(r[3]) : "r"(addr));
}
__device__ __forceinline__ void mma_fp16(float* c, const uint32_t* a, const uint32_t* b) {
    asm volatile(
        "mma.sync.aligned.m16n8k16.row.col.f32.f16.f16.f32 "
        "{%0,%1,%2,%3}, {%4,%5,%6,%7}, {%8,%9}, {%0,%1,%2,%3};"
        : "+f"(c[0]), "+f"(c[1]), "+f"(c[2]), "+f"(c[3])
        : "r"(a[0]), "r"(a[1]), "r"(a[2]), "r"(a[3]), "r"(b[0]), "r"(b[1]));
}

// swizzled offset within a 128x64B tile: row r (0..127), 16B chunk c (0..3)
__device__ __forceinline__ uint32_t swz(int r, int c) {
    return (uint32_t)r * 64u + (uint32_t)((c ^ ((r >> 1) & 3)) << 4);
}

// compensated accumulate: (s,c) += x*w with product error captured via FMA
__device__ __forceinline__ void comp_fma(float& s, float& c, float x, float w) {
    float p = x * w;
    float perr = fmaf(x, w, -p);
    float t = s + p;
    float z = t - s;
    float serr = (s - (t - z)) + (p - z);
    s = t;
    c += perr + serr;
}
__device__ __forceinline__ void comp_merge(float& s, float& c, float s2, float c2) {
    float t = s + s2;
    float z = t - s;
    float serr = (s - (t - z)) + (s2 - z);
    s = t;
    c += c2 + serr;
}

// ---------------- counter reset ----------------
__global__ void k_reset() { if (threadIdx.x < NE) g_counts[threadIdx.x] = 0; }

// ---------------- gating (top-2 per token, compensated fp32) ----------------
__global__ void k_gating(const float* __restrict__ x0, const float* __restrict__ Wg) {
    const int warp = threadIdx.x >> 5, lane = threadIdx.x & 31;
    const int t = blockIdx.x * (blockDim.x >> 5) + warp;
    float s[NE], c[NE];
#pragma unroll
    for (int e = 0; e < NE; e++) { s[e] = 0.f; c[e] = 0.f; }
    const float* x = x0 + (size_t)t * DM;
    for (int k = lane; k < DM; k += 32) {
        float xv = x[k];
        const float4 w0 = *reinterpret_cast<const float4*>(Wg + (size_t)k * NE);
        const float4 w1 = *reinterpret_cast<const float4*>(Wg + (size_t)k * NE + 4);
        comp_fma(s[0], c[0], xv, w0.x); comp_fma(s[1], c[1], xv, w0.y);
        comp_fma(s[2], c[2], xv, w0.z); comp_fma(s[3], c[3], xv, w0.w);
        comp_fma(s[4], c[4], xv, w1.x); comp_fma(s[5], c[5], xv, w1.y);
        comp_fma(s[6], c[6], xv, w1.z); comp_fma(s[7], c[7], xv, w1.w);
    }
#pragma unroll
    for (int off = 16; off > 0; off >>= 1)
#pragma unroll
        for (int e = 0; e < NE; e++) {
            float s2 = __shfl_xor_sync(0xffffffffu, s[e], off);
            float c2 = __shfl_xor_sync(0xffffffffu, c[e], off);
            comp_merge(s[e], c[e], s2, c2);
        }
    if (lane == 0) {
        double acc[NE];
#pragma unroll
        for (int e = 0; e < NE; e++) acc[e] = (double)s[e] + (double)c[e];
        int i1 = 0; double v1 = acc[0];
#pragma unroll
        for (int e = 1; e < NE; e++) if (acc[e] > v1) { v1 = acc[e]; i1 = e; }
        int i2 = -1; double v2 = -1.0e300;
#pragma unroll
        for (int e = 0; e < NE; e++) if (e != i1 && acc[e] > v2) { v2 = acc[e]; i2 = e; }
        g_top2[t] = i1 | (i2 << 8);
        atomicAdd(&g_counts[i1], 1);
        atomicAdd(&g_counts[i2], 1);
    }
}

// ---------------- cvt xl -> fp16 (vectorized) ----------------
__global__ void k_cvt_x(const float* __restrict__ x) {
    const size_t total4 = (size_t)TOKENS * DM / 4;
    const size_t stride = (size_t)gridDim.x * blockDim.x;
    for (size_t i = (size_t)blockIdx.x * blockDim.x + threadIdx.x; i < total4; i += stride) {
        float4 v = *reinterpret_cast<const float4*>(x + i * 4);
        __half2 h01 = __floats2half2_rn(v.x, v.y);
        __half2 h23 = __floats2half2_rn(v.z, v.w);
        *reinterpret_cast<uint2*>(g_xl + i * 4) =
            make_uint2(*(uint32_t*)&h01, *(uint32_t*)&h23);
    }
}

// ---------------- transpose-convert W[e][k][n] -> O[e][n][k] fp16 ----------
template <int K, int N, int MODE>
__global__ void k_wt(const float* __restrict__ W) {
    __shared__ float t[64][33];
    const int e = blockIdx.z;
    const int n0 = blockIdx.x * 32, k0 = blockIdx.y * 64;
    const float* Wp = W + (size_t)e * K * N;
    const int tx = threadIdx.x, ty = threadIdx.y;   // 32 x 8
#pragma unroll
    for (int j = 0; j < 8; j++)
        t[ty + j * 8][tx] = Wp[(size_t)(k0 + ty + j * 8) * N + n0 + tx];
    __syncthreads();
#pragma unroll
    for (int j = 0; j < 4; j++) {
        const int nl = ty + j * 8;
        __half2 h2 = __floats2half2_rn(t[tx * 2][nl], t[tx * 2 + 1][nl]);
        const size_t o = ((size_t)e * N + n0 + nl) * K + k0 + tx * 2;
        if (MODE == 0) *reinterpret_cast<uint32_t*>(g_w1t + o) = *(uint32_t*)&h2;
        else           *reinterpret_cast<uint32_t*>(g_w2t + o) = *(uint32_t*)&h2;
    }
}

// ---------------- scan (tiny) ----------------
__global__ void k_scan() {
    int s = 0;
    for (int e = 0; e < NE; e++) { g_offsets[e] = s; g_cursor[e] = s; s += g_counts[e]; }
}

// ---------------- parallel scatter ----------------
__global__ void k_scatter() {
    const int t = blockIdx.x * blockDim.x + threadIdx.x;
    const int p = g_top2[t];
    const int s1 = atomicAdd(&g_cursor[p & 0xff], 1);
    const int s2 = atomicAdd(&g_cursor[(p >> 8) & 0xff], 1);
    g_tokens[s1] = t;
    g_tokens[s2] = t;
}

// ---------------- plain fp16 grouped GEMM, fp32 accumulate ----------------
// GEMM1 epilogue: relu -> g_h (fp16). GEMM2 epilogue: atomicAdd into out
// (2 contributions/element over an exact-zero base: bitwise == separate combine).
template <int KT, int NTOT, bool IS_G1>
__global__ __launch_bounds__(256, 2) void k_hmma(const float* __restrict__ bias,
                                                 float* __restrict__ out) {
    const int e = blockIdx.z;
    const int cnt = g_counts[e];
    const int m0 = blockIdx.y * BM;
    if (m0 >= cnt) return;
    const int off = g_offsets[e];
    const int n0 = blockIdx.x * BN;
    const int tid = threadIdx.x;

    extern __shared__ char smem[];
    __shared__ int s_rows[BM];
    const uint32_t sb = smem_u32(smem);

    if (tid < BM) {
        int mm = m0 + tid;
        int mc = mm < cnt ? mm : cnt - 1;
        s_rows[tid] = IS_G1 ? g_tokens[off + mc] : (off + mc);
    }
    __syncthreads();

    const __half* A = IS_G1 ? g_xl : g_h;
    const __half* B = (IS_G1 ? g_w1t : g_w2t) + ((size_t)e * NTOT + n0) * KT;

    const int rF = tid >> 2, cF = tid & 3;
    const uint32_t d0 = swz(rF, cF);
    const uint32_t d1 = d0 + 64 * 64;
    const __half* a0 = A + (size_t)s_rows[rF] * KT + cF * 8;
    const __half* a1 = A + (size_t)s_rows[rF + 64] * KT + cF * 8;
    const __half* b0 = B + (size_t)rF * KT + cF * 8;
    const __half* b1 = B + (size_t)(rF + 64) * KT + cF * 8;

#define FILL(sidx, k0_) do {                                        \
        uint32_t _s = sb + (sidx) * STB;                            \
        cp_async16(_s + d0, a0 + (k0_));                            \
        cp_async16(_s + d1, a1 + (k0_));                            \
        cp_async16(_s + O_B + d0, b0 + (k0_));                      \
        cp_async16(_s + O_B + d1, b1 + (k0_));                      \
    } while (0)

    const int lane = tid & 31, wid = tid >> 5;
    const int warp_m = wid >> 2, warp_n = wid & 3;
    const int rowA = warp_m * 64 + (lane & 15);
    const int rowB = warp_n * 32 + ((lane >> 4) << 3) + (lane & 7);
    const uint32_t aoff = swz(rowA, lane >> 4);
    const uint32_t boff = swz(rowB, (lane >> 3) & 1);

    float acc[4][4][4];
#pragma unroll
    for (int i = 0; i < 4; i++)
#pragma unroll
        for (int j = 0; j < 4; j++)
#pragma unroll
            for (int q = 0; q < 4; q++) acc[i][j][q] = 0.f;

    constexpr int NKC = KT / BK;
    FILL(0, 0);       cp_commit();
    FILL(1, BK);      cp_commit();
    FILL(2, 2 * BK);  cp_commit();

    for (int kc = 0; kc < NKC; kc++) {
        cp_wait<2>();
        __syncthreads();
        if (kc + 3 < NKC) { FILL((kc + 3) % NSTG, (kc + 3) * BK); }
        cp_commit();
        const uint32_t st = sb + (kc % NSTG) * STB;
#pragma unroll
        for (int k16 = 0; k16 < 2; k16++) {
            const uint32_t ab = st + (aoff ^ (k16 << 5));
            const uint32_t bb = st + O_B + (boff ^ (k16 << 5));
            uint32_t af[4][4], bf[2][4];
#pragma unroll
            for (int mt = 0; mt < 4; mt++) ldsm4(af[mt], ab + mt * 1024);
#pragma unroll
            for (int p = 0; p < 2; p++)   ldsm4(bf[p], bb + p * 1024);
#pragma unroll
            for (int mt = 0; mt < 4; mt++)
#pragma unroll
                for (int nt = 0; nt < 4; nt++)
                    mma_fp16(acc[mt][nt], af[mt], &bf[nt >> 1][(nt & 1) * 2]);
        }
    }
#undef FILL

    // ---- epilogue ----
    const int g = lane >> 2, c2 = (lane & 3) * 2;
    const float* bp = bias + (size_t)e * NTOT;
#pragma unroll
    for (int mt = 0; mt < 4; mt++) {
#pragma unroll
        for (int nt = 0; nt < 4; nt++) {
            const int n = n0 + warp_n * 32 + nt * 8 + c2;
            const float bv0 = __ldg(bp + n), bv1 = __ldg(bp + n + 1);
#pragma unroll
            for (int h = 0; h < 2; h++) {
                const int m = m0 + warp_m * 64 + mt * 16 + g + h * 8;
                if (m >= cnt) continue;
                float v0 = acc[mt][nt][h * 2 + 0] + bv0;
                float v1 = acc[mt][nt][h * 2 + 1] + bv1;
                if (IS_G1) {
                    __half2 h2 = __floats2half2_rn(fmaxf(v0, 0.f), fmaxf(v1, 0.f));
                    *reinterpret_cast<uint32_t*>(g_h + (size_t)(off + m) * DH + n) =
                        *(uint32_t*)&h2;
                } else {
                    const int tok = g_tokens[off + m];
                    float* orow = out + (size_t)tok * DM + n;
                    atomicAdd(orow, v0);
                    atomicAdd(orow + 1, v1);
                }
            }
        }
    }
}

// ---------------- launch ----------------
extern "C" void kernel_launch(void* const* d_in, const int* in_sizes, int n_in,
                              void* d_out, int out_size) {
    const float* xl = (const float*)d_in[0];
    const float* x0 = (const float*)d_in[1];
    const float* Wg = (const float*)d_in[2];
    const float* W1 = (const float*)d_in[3];
    const float* b1 = (const float*)d_in[4];
    const float* W2 = (const float*)d_in[5];
    const float* b2 = (const float*)d_in[6];
    float* out = (float*)d_out;

    cudaFuncSetAttribute((const void*)k_hmma<DM, DH, true>,
                         cudaFuncAttributeMaxDynamicSharedMemorySize, SMEM_TOTAL);
    cudaFuncSetAttribute((const void*)k_hmma<DH, DM, false>,
                         cudaFuncAttributeMaxDynamicSharedMemorySize, SMEM_TOTAL);

    cudaMemsetAsync(out, 0, (size_t)TOKENS * DM * sizeof(float));
    k_reset<<<1, 32>>>();
    k_gating<<<TOKENS / 8, 256>>>(x0, Wg);
    k_cvt_x<<<512, 256>>>(xl);
    k_wt<DM, DH, 0><<<dim3(DH / 32, DM / 64, NE), dim3(32, 8)>>>(W1);
    k_wt<DH, DM, 1><<<dim3(DM / 32, DH / 64, NE), dim3(32, 8)>>>(W2);
    k_scan<<<1, 1>>>();
    k_scatter<<<TOKENS / 256, 256>>>();
    // GEMM1: fp16 1-pass, relu -> h (fp16)
    k_hmma<DM, DH, true><<<dim3(DH / BN, TOKENS / BM, NE), 256, SMEM_TOTAL>>>(b1, nullptr);
    // GEMM2: fp16 1-pass, atomic combine into out
    k_hmma<DH, DM, false><<<dim3(DM / BN, TOKENS / BM, NE), 256, SMEM_TOTAL>>>(b2, out);
}